// round 4
// baseline (speedup 1.0000x reference)
#include <cuda_runtime.h>
#include <math.h>

#define BATCH 128
#define CHN   3
#define IMH   135
#define IMW   240
#define NCH   (BATCH * CHN)
#define EPSV  1e-10f

// ---------------- scratch (device globals — no allocation) ----------------
__device__ float g_num[NCH];
__device__ float g_den[NCH];
__device__ float g_dot[BATCH];

// ---------------- init: zero accumulators every launch --------------------
__global__ void init_kernel() {
    int i = threadIdx.x;
    if (i < NCH)   { g_num[i] = 0.0f; g_den[i] = 0.0f; }
    if (i < BATCH) { g_dot[i] = 0.0f; }
}

// ---------------- fused separable VIF scale kernel -------------------------
// One block handles a TYxTX output tile of one channel-image for window N.
// Horizontal pass produces 5 partial-sum planes in smem, vertical pass
// finishes the 5 convolutions and does the VIF pointwise math + reduction.
template <int N, int TX, int TY>
__global__ __launch_bounds__(256)
void vif_scale(const float* __restrict__ R, const float* __restrict__ P) {
    constexpr int IH = TY + N - 1;
    constexpr int IW = TX + N - 1;
    constexpr int HO = IMH - N + 1;
    constexpr int WO = IMW - N + 1;

    __shared__ float sr [IH * IW];
    __shared__ float sp [IH * IW];
    __shared__ float hr [IH * TX];
    __shared__ float hp [IH * TX];
    __shared__ float hrr[IH * TX];
    __shared__ float hpp[IH * TX];
    __shared__ float hrp[IH * TX];
    __shared__ float wv [N];
    __shared__ float red[16];

    const int tid = threadIdx.x;
    const int ch  = blockIdx.z;
    const int ox0 = blockIdx.x * TX;
    const int oy0 = blockIdx.y * TY;

    // 1D Gaussian weights (normalized); separable product == reference 2D win.
    if (tid == 0) {
        const float sigma  = (float)N / 5.0f;
        const float inv2s2 = 1.0f / (2.0f * sigma * sigma);
        float s = 0.0f;
        #pragma unroll
        for (int i = 0; i < N; i++) {
            float d = (float)(i - N / 2);
            float v = expf(-d * d * inv2s2);
            wv[i] = v;
            s += v;
        }
        float inv = 1.0f / s;
        #pragma unroll
        for (int i = 0; i < N; i++) wv[i] *= inv;
    }

    // Load input tile (zero-fill outside image; outputs there are masked off).
    const float* r = R + (size_t)ch * (IMH * IMW);
    const float* p = P + (size_t)ch * (IMH * IMW);
    for (int idx = tid; idx < IH * IW; idx += 256) {
        int iy = idx / IW, ix = idx % IW;
        int gy = oy0 + iy, gx = ox0 + ix;
        float rv = 0.0f, pv = 0.0f;
        if (gy < IMH && gx < IMW) {
            rv = r[gy * IMW + gx];
            pv = p[gy * IMW + gx];
        }
        sr[idx] = rv;
        sp[idx] = pv;
    }
    __syncthreads();

    // Horizontal pass: 5 windowed sums along x.
    for (int idx = tid; idx < IH * TX; idx += 256) {
        int hy = idx / TX, hx = idx % TX;
        const float* rrow = &sr[hy * IW + hx];
        const float* prow = &sp[hy * IW + hx];
        float ar = 0.f, ap = 0.f, arr = 0.f, app = 0.f, arp = 0.f;
        #pragma unroll
        for (int j = 0; j < N; j++) {
            float w = wv[j];
            float a = rrow[j];
            float b = prow[j];
            ar  += w * a;
            ap  += w * b;
            arr += w * a * a;
            app += w * b * b;
            arp += w * a * b;
        }
        hr [idx] = ar;
        hp [idx] = ap;
        hrr[idx] = arr;
        hpp[idx] = app;
        hrp[idx] = arp;
    }
    __syncthreads();

    // Vertical pass + VIF pointwise math (mask order replicated exactly).
    float numa = 0.0f, dena = 0.0f;
    for (int idx = tid; idx < TY * TX; idx += 256) {
        int y = idx / TX, x = idx % TX;
        if (oy0 + y >= HO || ox0 + x >= WO) continue;
        float m1 = 0.f, m2 = 0.f, srr = 0.f, spp = 0.f, srp = 0.f;
        #pragma unroll
        for (int i = 0; i < N; i++) {
            float w = wv[i];
            int   o = (y + i) * TX + x;
            m1  += w * hr [o];
            m2  += w * hp [o];
            srr += w * hrr[o];
            spp += w * hpp[o];
            srp += w * hrp[o];
        }
        float sigGT = fmaxf(srr - m1 * m1, 0.0f);
        float sigP  = fmaxf(spp - m2 * m2, 0.0f);
        float sigGP = srp - m1 * m2;
        float g  = sigGP / (sigGT + EPSV);
        float sv = sigP - g * sigGP;
        if (sigGT < EPSV) { g = 0.0f; sv = sigP; sigGT = 0.0f; }
        if (sigP  < EPSV) { g = 0.0f; sv = 0.0f; }
        if (g < 0.0f)     { sv = sigP; g = 0.0f; }
        if (sv <= EPSV)   sv = EPSV;
        numa += log10f(1.0f + g * g * sigGT / (sv + 2.0f));
        dena += log10f(1.0f + sigGT * 0.5f);
    }

    // Block reduction (8 warps) -> per-channel atomics.
    #pragma unroll
    for (int o = 16; o > 0; o >>= 1) {
        numa += __shfl_down_sync(0xFFFFFFFFu, numa, o);
        dena += __shfl_down_sync(0xFFFFFFFFu, dena, o);
    }
    if ((tid & 31) == 0) {
        red[tid >> 5]     = numa;
        red[8 + (tid >> 5)] = dena;
    }
    __syncthreads();
    if (tid == 0) {
        float n = 0.f, d = 0.f;
        #pragma unroll
        for (int w = 0; w < 8; w++) { n += red[w]; d += red[8 + w]; }
        atomicAdd(&g_num[ch], n);
        atomicAdd(&g_den[ch], d);
    }
}

// ---------------- prediction term: per-image dot((x - r), W) ---------------
__global__ __launch_bounds__(1024)
void pred_kernel(const float* __restrict__ R, const float* __restrict__ X,
                 const float* __restrict__ Wl) {
    const int img = blockIdx.x;
    const int n   = CHN * IMH * IMW;  // 97200
    const float* r = R + (size_t)img * n;
    const float* x = X + (size_t)img * n;
    float acc = 0.0f;
    for (int i = threadIdx.x; i < n; i += 1024)
        acc += (x[i] - r[i]) * Wl[i];

    __shared__ float red[32];
    #pragma unroll
    for (int o = 16; o > 0; o >>= 1)
        acc += __shfl_down_sync(0xFFFFFFFFu, acc, o);
    if ((threadIdx.x & 31) == 0) red[threadIdx.x >> 5] = acc;
    __syncthreads();
    if (threadIdx.x < 32) {
        float v = red[threadIdx.x];
        #pragma unroll
        for (int o = 16; o > 0; o >>= 1)
            v += __shfl_down_sync(0xFFFFFFFFu, v, o);
        if (threadIdx.x == 0) g_dot[img] = v;
    }
}

// ---------------- final: assemble the 3 scalars ----------------------------
__global__ void final_kernel(float* __restrict__ out) {
    const int t = threadIdx.x;  // 128 threads, one per image
    float vif = 0.0f;
    #pragma unroll
    for (int c = 0; c < CHN; c++) {
        int ch = t * CHN + c;
        vif += g_num[ch] / g_den[ch];
    }
    vif *= (1.0f / CHN);
    float rl = 1.0f - vif;
    float d  = g_dot[t];
    float pl = d * d;

    __shared__ float red[8];
    #pragma unroll
    for (int o = 16; o > 0; o >>= 1) {
        rl += __shfl_down_sync(0xFFFFFFFFu, rl, o);
        pl += __shfl_down_sync(0xFFFFFFFFu, pl, o);
    }
    if ((t & 31) == 0) {
        red[t >> 5]     = rl;
        red[4 + (t >> 5)] = pl;
    }
    __syncthreads();
    if (t == 0) {
        float rls = 0.f, pls = 0.f;
        #pragma unroll
        for (int w = 0; w < 4; w++) { rls += red[w]; pls += red[4 + w]; }
        rls *= (1.0f / BATCH);
        pls *= (1.0f / BATCH);
        out[0] = pls + rls;  // loss
        out[1] = rls;        // recons_loss
        out[2] = pls;        // prediction_loss
    }
}

// ---------------- launch ---------------------------------------------------
extern "C" void kernel_launch(void* const* d_in, const int* in_sizes, int n_in,
                              void* d_out, int out_size) {
    const float* recons = (const float*)d_in[0];
    const float* x      = (const float*)d_in[1];
    const float* Wl     = (const float*)d_in[2];
    // d_in[3] = b, cancels exactly in (pred_orig - pred_recons)
    float* out = (float*)d_out;

    init_kernel<<<1, 384>>>();

    dim3 blk(256);
    // scale 1: N=17, out 119x224
    {
        dim3 g((224 + 31) / 32, (119 + 23) / 24, NCH);
        vif_scale<17, 32, 24><<<g, blk>>>(recons, x);
    }
    // scale 2: N=9, out 127x232
    {
        dim3 g((232 + 31) / 32, (127 + 31) / 32, NCH);
        vif_scale<9, 32, 32><<<g, blk>>>(recons, x);
    }
    // scale 3: N=5, out 131x236
    {
        dim3 g((236 + 31) / 32, (131 + 31) / 32, NCH);
        vif_scale<5, 32, 32><<<g, blk>>>(recons, x);
    }
    // scale 4: N=3, out 133x238
    {
        dim3 g((238 + 31) / 32, (133 + 31) / 32, NCH);
        vif_scale<3, 32, 32><<<g, blk>>>(recons, x);
    }

    pred_kernel<<<BATCH, 1024>>>(recons, x, Wl);
    final_kernel<<<1, 128>>>(out);
}

// round 6
// speedup vs baseline: 1.3043x; 1.3043x over previous
#include <cuda_runtime.h>
#include <math.h>

#define BATCH 128
#define CHN   3
#define IMH   135
#define IMW   240
#define NCH   (BATCH * CHN)
#define EPSV  1e-10f

typedef unsigned long long u64;

// ---------------- packed f32x2 helpers (sm_103a) ---------------------------
__device__ __forceinline__ u64 pk(float lo, float hi) {
    u64 r;
    asm("mov.b64 %0, {%1,%2};" : "=l"(r) : "f"(lo), "f"(hi));
    return r;
}
__device__ __forceinline__ void upk(u64 v, float& lo, float& hi) {
    asm("mov.b64 {%0,%1}, %2;" : "=f"(lo), "=f"(hi) : "l"(v));
}
__device__ __forceinline__ u64 fma2(u64 a, u64 b, u64 c) {
    u64 d;
    asm("fma.rn.f32x2 %0, %1, %2, %3;" : "=l"(d) : "l"(a), "l"(b), "l"(c));
    return d;
}
__device__ __forceinline__ u64 mul2(u64 a, u64 b) {
    u64 d;
    asm("mul.rn.f32x2 %0, %1, %2;" : "=l"(d) : "l"(a), "l"(b));
    return d;
}

// ---------------- scratch (device globals — no allocation) ----------------
__device__ float g_num[NCH];
__device__ float g_den[NCH];
__device__ float g_dot[BATCH];
__device__ u64   g_w2[4][17];   // packed (w,w) Gaussian weights per scale

// ---------------- init: zero accumulators + weights every launch -----------
__global__ void init_kernel() {
    int i = threadIdx.x;
    if (i < NCH)   { g_num[i] = 0.0f; g_den[i] = 0.0f; }
    if (i < BATCH) { g_dot[i] = 0.0f; }
    if (i == 0) {
        const int Ns[4] = {17, 9, 5, 3};
        for (int s = 0; s < 4; s++) {
            int n = Ns[s];
            float sigma  = (float)n / 5.0f;
            float inv2s2 = 1.0f / (2.0f * sigma * sigma);
            float wv[17];
            float sum = 0.0f;
            for (int j = 0; j < n; j++) {
                float d = (float)(j - n / 2);
                float v = expf(-d * d * inv2s2);
                wv[j] = v;
                sum += v;
            }
            float is = 1.0f / sum;
            for (int j = 0; j < n; j++) {
                float w = wv[j] * is;
                g_w2[s][j] = pk(w, w);
            }
        }
    }
}

// ---------------- fused separable VIF scale kernel -------------------------
// 256 threads = 32 lanes (x) x 8 row-groups. TX=32 output cols, TY=8*KY rows.
// Horizontal pass -> packed planes in smem; vertical pass register-blocked
// KY outputs/thread; fast-math pointwise; lg2 accumulation (log10 scale
// cancels in num/den ratio).
template <int N, int TY, int KY, int SIDX>
__global__ __launch_bounds__(256)
void vif_scale(const float* __restrict__ R, const float* __restrict__ P) {
    static_assert(TY == 8 * KY, "thread layout");
    constexpr int IH = TY + N - 1;
    constexpr int IW = 32 + N - 1;
    constexpr int HO = IMH - N + 1;
    constexpr int WO = IMW - N + 1;

    __shared__ u64        s2[IH * IW];   // interleaved (r,p)
    __shared__ ulonglong2 h4[IH * 32];   // {(hr,hp),(hrr,hpp)}
    __shared__ float      hc[IH * 32];   // hrp
    __shared__ float      red[16];

    const int tid = threadIdx.x;
    const int tx  = tid & 31;
    const int wy  = tid >> 5;
    const int ch  = blockIdx.z;
    const int ox0 = blockIdx.x * 32;
    const int oy0 = blockIdx.y * TY;

    // weights into registers (packed (w,w))
    u64 ww[N];
    #pragma unroll
    for (int j = 0; j < N; j++) ww[j] = g_w2[SIDX][j];

    // ---- load tile (zero-fill outside image) ----
    const float* __restrict__ r = R + (size_t)ch * (IMH * IMW);
    const float* __restrict__ p = P + (size_t)ch * (IMH * IMW);
    for (int row = wy; row < IH; row += 8) {
        int gy = oy0 + row;
        bool yok = gy < IMH;
        #pragma unroll
        for (int col = tx; col < IW; col += 32) {
            int gx = ox0 + col;
            float rv = 0.0f, pv = 0.0f;
            if (yok && gx < IMW) {
                rv = r[gy * IMW + gx];
                pv = p[gy * IMW + gx];
            }
            s2[row * IW + col] = pk(rv, pv);
        }
    }
    __syncthreads();

    // ---- horizontal pass ----
    for (int row = wy; row < IH; row += 8) {
        int base = row * IW + tx;
        u64 acc1 = 0ull;   // (ar, ap)
        u64 acc2 = 0ull;   // (arr, app)
        float arp = 0.0f;
        #pragma unroll
        for (int j = 0; j < N; j++) {
            u64 u = s2[base + j];
            acc1 = fma2(ww[j], u, acc1);
            u64 t = mul2(ww[j], u);          // (wa, wb)
            acc2 = fma2(t, u, acc2);
            float wa, wb, a, b;
            upk(t, wa, wb);
            upk(u, a, b);
            arp = fmaf(wa, b, arp);
        }
        h4[row * 32 + tx] = make_ulonglong2(acc1, acc2);
        hc[row * 32 + tx] = arp;
    }
    __syncthreads();

    // ---- vertical pass + pointwise, KY outputs per thread ----
    const int y0 = wy * KY;
    u64   m12[KY];
    u64   qq [KY];
    float srp[KY];
    #pragma unroll
    for (int k = 0; k < KY; k++) { m12[k] = 0ull; qq[k] = 0ull; srp[k] = 0.0f; }

    #pragma unroll
    for (int t = 0; t < KY + N - 1; t++) {
        int row = y0 + t;
        ulonglong2 h = h4[row * 32 + tx];
        float c = hc[row * 32 + tx];
        #pragma unroll
        for (int k = 0; k < KY; k++) {
            int j = t - k;
            if (j >= 0 && j < N) {
                m12[k] = fma2(ww[j], h.x, m12[k]);
                qq [k] = fma2(ww[j], h.y, qq [k]);
                float wj, wd;
                upk(ww[j], wj, wd);
                srp[k] = fmaf(wj, c, srp[k]);
            }
        }
    }

    float numa = 0.0f, dena = 0.0f;
    const bool xok = (ox0 + tx) < WO;
    #pragma unroll
    for (int k = 0; k < KY; k++) {
        float m1, m2, srr, spp;
        upk(m12[k], m1, m2);
        upk(qq[k], srr, spp);
        float sGT = fmaxf(srr - m1 * m1, 0.0f);
        float sP  = fmaxf(spp - m2 * m2, 0.0f);
        float sGP = srp[k] - m1 * m2;
        float g  = __fdividef(sGP, sGT + EPSV);
        float sv = sP - g * sGP;
        if (sGT < EPSV) { g = 0.0f; sv = sP; sGT = 0.0f; }
        if (sP  < EPSV) { g = 0.0f; sv = 0.0f; }
        if (g < 0.0f)   { sv = sP; g = 0.0f; }
        if (sv <= EPSV) sv = EPSV;
        // lg2 sums: log10 constant cancels in num/den ratio
        float na = __log2f(fmaf(g * g, __fdividef(sGT, sv + 2.0f), 1.0f));
        float da = __log2f(fmaf(sGT, 0.5f, 1.0f));
        if (xok && (oy0 + y0 + k) < HO) {
            numa += na;
            dena += da;
        }
    }

    // ---- block reduction -> per-channel atomics ----
    #pragma unroll
    for (int o = 16; o > 0; o >>= 1) {
        numa += __shfl_down_sync(0xFFFFFFFFu, numa, o);
        dena += __shfl_down_sync(0xFFFFFFFFu, dena, o);
    }
    if (tx == 0) {
        red[wy]     = numa;
        red[8 + wy] = dena;
    }
    __syncthreads();
    if (tid == 0) {
        float n = 0.f, d = 0.f;
        #pragma unroll
        for (int w = 0; w < 8; w++) { n += red[w]; d += red[8 + w]; }
        atomicAdd(&g_num[ch], n);
        atomicAdd(&g_den[ch], d);
    }
}

// ---------------- prediction term: per-image dot((x - r), W) ---------------
__global__ __launch_bounds__(1024)
void pred_kernel(const float* __restrict__ R, const float* __restrict__ X,
                 const float* __restrict__ Wl) {
    const int img = blockIdx.x;
    const int n4  = (CHN * IMH * IMW) / 4;  // 24300
    const float4* r4 = (const float4*)(R + (size_t)img * (CHN * IMH * IMW));
    const float4* x4 = (const float4*)(X + (size_t)img * (CHN * IMH * IMW));
    const float4* w4 = (const float4*)Wl;
    float acc = 0.0f;
    for (int i = threadIdx.x; i < n4; i += 1024) {
        float4 a = x4[i], b = r4[i], w = w4[i];
        acc = fmaf(a.x - b.x, w.x, acc);
        acc = fmaf(a.y - b.y, w.y, acc);
        acc = fmaf(a.z - b.z, w.z, acc);
        acc = fmaf(a.w - b.w, w.w, acc);
    }
    __shared__ float red[32];
    #pragma unroll
    for (int o = 16; o > 0; o >>= 1)
        acc += __shfl_down_sync(0xFFFFFFFFu, acc, o);
    if ((threadIdx.x & 31) == 0) red[threadIdx.x >> 5] = acc;
    __syncthreads();
    if (threadIdx.x < 32) {
        float v = red[threadIdx.x];
        #pragma unroll
        for (int o = 16; o > 0; o >>= 1)
            v += __shfl_down_sync(0xFFFFFFFFu, v, o);
        if (threadIdx.x == 0) g_dot[img] = v;
    }
}

// ---------------- final: assemble the 3 scalars ----------------------------
__global__ void final_kernel(float* __restrict__ out) {
    const int t = threadIdx.x;  // 128 threads, one per image
    float vif = 0.0f;
    #pragma unroll
    for (int c = 0; c < CHN; c++) {
        int ch = t * CHN + c;
        vif += g_num[ch] / g_den[ch];
    }
    vif *= (1.0f / CHN);
    float rl = 1.0f - vif;
    float d  = g_dot[t];
    float pl = d * d;

    __shared__ float red[8];
    #pragma unroll
    for (int o = 16; o > 0; o >>= 1) {
        rl += __shfl_down_sync(0xFFFFFFFFu, rl, o);
        pl += __shfl_down_sync(0xFFFFFFFFu, pl, o);
    }
    if ((t & 31) == 0) {
        red[t >> 5]       = rl;
        red[4 + (t >> 5)] = pl;
    }
    __syncthreads();
    if (t == 0) {
        float rls = 0.f, pls = 0.f;
        #pragma unroll
        for (int w = 0; w < 4; w++) { rls += red[w]; pls += red[4 + w]; }
        rls *= (1.0f / BATCH);
        pls *= (1.0f / BATCH);
        out[0] = pls + rls;  // loss
        out[1] = rls;        // recons_loss
        out[2] = pls;        // prediction_loss
    }
}

// ---------------- launch ---------------------------------------------------
extern "C" void kernel_launch(void* const* d_in, const int* in_sizes, int n_in,
                              void* d_out, int out_size) {
    const float* recons = (const float*)d_in[0];
    const float* x      = (const float*)d_in[1];
    const float* Wl     = (const float*)d_in[2];
    // d_in[3] = b, cancels exactly in (pred_orig - pred_recons)
    float* out = (float*)d_out;

    init_kernel<<<1, 384>>>();

    dim3 blk(256);
    // scale 1: N=17, out 119x224  -> gx=7, gy=ceil(119/24)=5
    {
        dim3 g(7, 5, NCH);
        vif_scale<17, 24, 3, 0><<<g, blk>>>(recons, x);
    }
    // scale 2: N=9, out 127x232   -> gx=8, gy=ceil(127/32)=4
    {
        dim3 g(8, 4, NCH);
        vif_scale<9, 32, 4, 1><<<g, blk>>>(recons, x);
    }
    // scale 3: N=5, out 131x236   -> gx=8, gy=ceil(131/32)=5
    {
        dim3 g(8, 5, NCH);
        vif_scale<5, 32, 4, 2><<<g, blk>>>(recons, x);
    }
    // scale 4: N=3, out 133x238   -> gx=8, gy=ceil(133/32)=5
    {
        dim3 g(8, 5, NCH);
        vif_scale<3, 32, 4, 3><<<g, blk>>>(recons, x);
    }

    pred_kernel<<<BATCH, 1024>>>(recons, x, Wl);
    final_kernel<<<1, 128>>>(out);
}

// round 7
// speedup vs baseline: 1.3514x; 1.0361x over previous
#include <cuda_runtime.h>
#include <math.h>

#define BATCH 128
#define CHN   3
#define IMH   135
#define IMW   240
#define NCH   (BATCH * CHN)
#define EPSV  1e-10f

typedef unsigned long long u64;

// ---------------- packed f32x2 helpers (sm_103a) ---------------------------
__device__ __forceinline__ u64 pk(float lo, float hi) {
    u64 r; asm("mov.b64 %0, {%1,%2};" : "=l"(r) : "f"(lo), "f"(hi)); return r;
}
__device__ __forceinline__ void upk(u64 v, float& lo, float& hi) {
    asm("mov.b64 {%0,%1}, %2;" : "=f"(lo), "=f"(hi) : "l"(v));
}
__device__ __forceinline__ u64 fma2(u64 a, u64 b, u64 c) {
    u64 d; asm("fma.rn.f32x2 %0, %1, %2, %3;" : "=l"(d) : "l"(a), "l"(b), "l"(c)); return d;
}
__device__ __forceinline__ u64 mul2(u64 a, u64 b) {
    u64 d; asm("mul.rn.f32x2 %0, %1, %2;" : "=l"(d) : "l"(a), "l"(b)); return d;
}
__device__ __forceinline__ u64 add2(u64 a, u64 b) {
    u64 d; asm("add.rn.f32x2 %0, %1, %2;" : "=l"(d) : "l"(a), "l"(b)); return d;
}
// (a.hi, b.lo) — odd-tap pair from two neighboring even pairs
__device__ __forceinline__ u64 mid(u64 a, u64 b) {
    float al, ah, bl, bh; upk(a, al, ah); upk(b, bl, bh); return pk(ah, bl);
}

// ---------------- scratch (device globals — no allocation) ----------------
__device__ float g_num[NCH];
__device__ float g_den[NCH];
__device__ float g_dot[BATCH];
__device__ u64   g_w2[4][9];   // packed (w,w); symmetric half j=0..(N-1)/2

// ---------------- init: zero accumulators + weights every launch -----------
__global__ void init_kernel() {
    int i = threadIdx.x;
    if (i < NCH)   { g_num[i] = 0.0f; g_den[i] = 0.0f; }
    if (i < BATCH) { g_dot[i] = 0.0f; }
    if (i == 0) {
        const int Ns[4] = {17, 9, 5, 3};
        for (int s = 0; s < 4; s++) {
            int n = Ns[s];
            float sigma  = (float)n / 5.0f;
            float inv2s2 = 1.0f / (2.0f * sigma * sigma);
            float wv[17];
            float sum = 0.0f;
            for (int j = 0; j < n; j++) {
                float d = (float)(j - n / 2);
                float v = expf(-d * d * inv2s2);
                wv[j] = v;
                sum += v;
            }
            float is = 1.0f / sum;
            for (int j = 0; j < (n + 1) / 2; j++) {
                float w = wv[j] * is;
                g_w2[s][j] = pk(w, w);
            }
        }
    }
}

// ---------------- fused separable VIF scale kernel -------------------------
// 256 threads = 16 lanes (each owning 2 adjacent x outputs) x 16 y-groups.
// TX = 32 output cols. All conv quantities packed by x-pair (f32x2), so every
// hot-loop op is one packed FMA covering two outputs with no unpacking.
template <int N, int KY, int SIDX>
__global__ __launch_bounds__(256)
void vif_scale(const float* __restrict__ R, const float* __restrict__ P) {
    constexpr int TY = 16 * KY;
    constexpr int IH = TY + N - 1;
    constexpr int IW = 32 + N - 1;       // even (N odd) -> LDS.64 stays aligned
    constexpr int HO = IMH - N + 1;
    constexpr int WO = IMW - N + 1;
    constexpr int HLF = (N - 1) / 2;
    constexpr int NH = (N + 1) / 2;
    constexpr int SMB = 8 * IH * IW + 640 * IH;   // inputs + 5 packed planes
    static_assert(SMB <= 49152, "static smem limit");

    __shared__ __align__(16) char SM[SMB];
    float*      s_r = (float*)SM;
    float*      s_p = s_r + IH * IW;
    ulonglong2* hA  = (ulonglong2*)(SM + 8 * IH * IW);  // (hr2, hp2)
    ulonglong2* hB  = hA + IH * 16;                     // (hrr2, hpp2)
    u64*        hC  = (u64*)(hB + IH * 16);             // hrp2
    float*      red = (float*)SM;  // aliases inputs — dead after horizontal

    const int tid  = threadIdx.x;
    const int lane = tid & 15;
    const int yg   = tid >> 4;
    const int ch   = blockIdx.z;
    const int ox0  = blockIdx.x * 32;
    const int oy0  = blockIdx.y * TY;

    u64 ww[NH];
    #pragma unroll
    for (int j = 0; j < NH; j++) ww[j] = g_w2[SIDX][j];

    // ---- load tile (zero-fill outside image; invalid outputs masked) ----
    const float* __restrict__ r = R + (size_t)ch * (IMH * IMW);
    const float* __restrict__ p = P + (size_t)ch * (IMH * IMW);
    for (int idx = tid; idx < IH * IW; idx += 256) {
        int iy = idx / IW, ix = idx - iy * IW;
        int gy = oy0 + iy, gx = ox0 + ix;
        float rv = 0.0f, pv = 0.0f;
        if (gy < IMH && gx < IMW) {
            int o = gy * IMW + gx;
            rv = r[o]; pv = p[o];
        }
        s_r[idx] = rv; s_p[idx] = pv;
    }
    __syncthreads();

    // ---- horizontal pass: 5 packed windowed sums for 2 adjacent outputs ----
    for (int row = yg; row < IH; row += 16) {
        const int base = row * IW + 2 * lane;   // even -> LDS.64 aligned
        u64 ar = 0, ap = 0, arr = 0, app = 0, arp = 0;
        u64 rl = *(const u64*)&s_r[base];
        u64 pl = *(const u64*)&s_p[base];
        {   // tap 0
            u64 w  = ww[0];
            u64 tr = mul2(w, rl), tp = mul2(w, pl);
            ar = add2(ar, tr); ap = add2(ap, tp);
            arr = fma2(tr, rl, arr); app = fma2(tp, pl, app); arp = fma2(tr, pl, arp);
        }
        #pragma unroll
        for (int j2 = 2; j2 < N; j2 += 2) {
            u64 rn = *(const u64*)&s_r[base + j2];
            u64 pn = *(const u64*)&s_p[base + j2];
            {   // even tap j2
                u64 w  = ww[(j2 <= HLF) ? j2 : (N - 1 - j2)];
                u64 tr = mul2(w, rn), tp = mul2(w, pn);
                ar = add2(ar, tr); ap = add2(ap, tp);
                arr = fma2(tr, rn, arr); app = fma2(tp, pn, app); arp = fma2(tr, pn, arp);
            }
            {   // odd tap j2-1, pair built from neighbor halves
                constexpr int dummy = 0; (void)dummy;
                int jm = j2 - 1;
                u64 w  = ww[(jm <= HLF) ? jm : (N - 1 - jm)];
                u64 rm = mid(rl, rn), pm = mid(pl, pn);
                u64 tr = mul2(w, rm), tp = mul2(w, pm);
                ar = add2(ar, tr); ap = add2(ap, tp);
                arr = fma2(tr, rm, arr); app = fma2(tp, pm, app); arp = fma2(tr, pm, arp);
            }
            rl = rn; pl = pn;
        }
        hA[row * 16 + lane] = make_ulonglong2(ar, ap);
        hB[row * 16 + lane] = make_ulonglong2(arr, app);
        hC[row * 16 + lane] = arp;
    }
    __syncthreads();

    // ---- vertical pass: KY packed output-rows per thread ----
    const int y0 = yg * KY;
    u64 am1[KY], am2[KY], vrr[KY], vpp[KY], vrp[KY];
    #pragma unroll
    for (int k = 0; k < KY; k++) { am1[k] = 0; am2[k] = 0; vrr[k] = 0; vpp[k] = 0; vrp[k] = 0; }

    #pragma unroll
    for (int t = 0; t < KY + N - 1; t++) {
        int row = y0 + t;
        ulonglong2 A = hA[row * 16 + lane];
        ulonglong2 B = hB[row * 16 + lane];
        u64        C = hC[row * 16 + lane];
        #pragma unroll
        for (int k = 0; k < KY; k++) {
            int j = t - k;
            if (j >= 0 && j < N) {           // static in unrolled loops
                u64 w = ww[(j <= HLF) ? j : (N - 1 - j)];
                am1[k] = fma2(w, A.x, am1[k]);
                am2[k] = fma2(w, A.y, am2[k]);
                vrr[k] = fma2(w, B.x, vrr[k]);
                vpp[k] = fma2(w, B.y, vpp[k]);
                vrp[k] = fma2(w, C,   vrp[k]);
            }
        }
    }

    // ---- pointwise (collapsed mask logic; lg2 — log10 cancels in ratio) ----
    float numa = 0.0f, dena = 0.0f;
    const int oxb = ox0 + 2 * lane;
    #pragma unroll
    for (int k = 0; k < KY; k++) {
        if (oy0 + y0 + k >= HO) continue;
        float m1[2], m2[2], rr[2], pp[2], rp[2];
        upk(am1[k], m1[0], m1[1]);
        upk(am2[k], m2[0], m2[1]);
        upk(vrr[k], rr[0], rr[1]);
        upk(vpp[k], pp[0], pp[1]);
        upk(vrp[k], rp[0], rp[1]);
        #pragma unroll
        for (int c = 0; c < 2; c++) {
            if (oxb + c >= WO) continue;
            float sGT = fmaxf(rr[c] - m1[c] * m1[c], 0.0f);
            float sP  = fmaxf(pp[c] - m2[c] * m2[c], 0.0f);
            float sGP = rp[c] - m1[c] * m2[c];
            // num != 0 only when all reference masks are un-triggered:
            bool cond = (sGT >= EPSV) && (sP >= EPSV) && (sGP > 0.0f);
            float g  = cond ? __fdividef(sGP, sGT + EPSV) : 0.0f;
            float sv = fmaxf(sP - g * sGP, EPSV);
            numa += __log2f(fmaf(g * g, __fdividef(sGT, sv + 2.0f), 1.0f));
            // den: sGT<EPS -> 1+sGT/2 rounds to 1.0f -> log = 0, same as masked
            dena += __log2f(fmaf(sGT, 0.5f, 1.0f));
        }
    }

    // ---- reduction -> per-channel atomics ----
    #pragma unroll
    for (int o = 16; o > 0; o >>= 1) {
        numa += __shfl_down_sync(0xFFFFFFFFu, numa, o);
        dena += __shfl_down_sync(0xFFFFFFFFu, dena, o);
    }
    if ((tid & 31) == 0) {
        red[tid >> 5]       = numa;
        red[8 + (tid >> 5)] = dena;
    }
    __syncthreads();
    if (tid == 0) {
        float n = 0.f, d = 0.f;
        #pragma unroll
        for (int w = 0; w < 8; w++) { n += red[w]; d += red[8 + w]; }
        atomicAdd(&g_num[ch], n);
        atomicAdd(&g_den[ch], d);
    }
}

// ---------------- prediction term: per-image dot((x - r), W) ---------------
__global__ __launch_bounds__(1024)
void pred_kernel(const float* __restrict__ R, const float* __restrict__ X,
                 const float* __restrict__ Wl) {
    const int img = blockIdx.x;
    const int n4  = (CHN * IMH * IMW) / 4;  // 24300
    const float4* r4 = (const float4*)(R + (size_t)img * (CHN * IMH * IMW));
    const float4* x4 = (const float4*)(X + (size_t)img * (CHN * IMH * IMW));
    const float4* w4 = (const float4*)Wl;
    float acc = 0.0f;
    for (int i = threadIdx.x; i < n4; i += 1024) {
        float4 a = x4[i], b = r4[i], w = w4[i];
        acc = fmaf(a.x - b.x, w.x, acc);
        acc = fmaf(a.y - b.y, w.y, acc);
        acc = fmaf(a.z - b.z, w.z, acc);
        acc = fmaf(a.w - b.w, w.w, acc);
    }
    __shared__ float red[32];
    #pragma unroll
    for (int o = 16; o > 0; o >>= 1)
        acc += __shfl_down_sync(0xFFFFFFFFu, acc, o);
    if ((threadIdx.x & 31) == 0) red[threadIdx.x >> 5] = acc;
    __syncthreads();
    if (threadIdx.x < 32) {
        float v = red[threadIdx.x];
        #pragma unroll
        for (int o = 16; o > 0; o >>= 1)
            v += __shfl_down_sync(0xFFFFFFFFu, v, o);
        if (threadIdx.x == 0) g_dot[img] = v;
    }
}

// ---------------- final: assemble the 3 scalars ----------------------------
__global__ void final_kernel(float* __restrict__ out) {
    const int t = threadIdx.x;  // 128 threads, one per image
    float vif = 0.0f;
    #pragma unroll
    for (int c = 0; c < CHN; c++) {
        int ch = t * CHN + c;
        vif += g_num[ch] / g_den[ch];
    }
    vif *= (1.0f / CHN);
    float rl = 1.0f - vif;
    float d  = g_dot[t];
    float pl = d * d;

    __shared__ float red[8];
    #pragma unroll
    for (int o = 16; o > 0; o >>= 1) {
        rl += __shfl_down_sync(0xFFFFFFFFu, rl, o);
        pl += __shfl_down_sync(0xFFFFFFFFu, pl, o);
    }
    if ((t & 31) == 0) {
        red[t >> 5]       = rl;
        red[4 + (t >> 5)] = pl;
    }
    __syncthreads();
    if (t == 0) {
        float rls = 0.f, pls = 0.f;
        #pragma unroll
        for (int w = 0; w < 4; w++) { rls += red[w]; pls += red[4 + w]; }
        rls *= (1.0f / BATCH);
        pls *= (1.0f / BATCH);
        out[0] = pls + rls;  // loss
        out[1] = rls;        // recons_loss
        out[2] = pls;        // prediction_loss
    }
}

// ---------------- launch ---------------------------------------------------
extern "C" void kernel_launch(void* const* d_in, const int* in_sizes, int n_in,
                              void* d_out, int out_size) {
    const float* recons = (const float*)d_in[0];
    const float* x      = (const float*)d_in[1];
    const float* Wl     = (const float*)d_in[2];
    // d_in[3] = b, cancels exactly in (pred_orig - pred_recons)
    float* out = (float*)d_out;

    init_kernel<<<1, 384>>>();

    dim3 blk(256);
    // scale 1: N=17, out 119x224, TY=32 -> grid 7x4   (smem 49152 exactly)
    vif_scale<17, 2, 0><<<dim3(7, 4, NCH), blk>>>(recons, x);
    // scale 2: N=9,  out 127x232, TY=32 -> grid 8x4   (smem 38400)
    vif_scale< 9, 2, 1><<<dim3(8, 4, NCH), blk>>>(recons, x);
    // scale 3: N=5,  out 131x236, TY=48 -> grid 8x3   (smem 48256)
    vif_scale< 5, 3, 2><<<dim3(8, 3, NCH), blk>>>(recons, x);
    // scale 4: N=3,  out 133x238, TY=48 -> grid 8x3   (smem 45600)
    vif_scale< 3, 3, 3><<<dim3(8, 3, NCH), blk>>>(recons, x);

    pred_kernel<<<BATCH, 1024>>>(recons, x, Wl);
    final_kernel<<<1, 128>>>(out);
}